// round 11
// baseline (speedup 1.0000x reference)
#include <cuda_runtime.h>
#include <cuda_fp16.h>
#include <cstdint>

// LUTBlock: out[b,o] = sum_{t=0..15} table[t, idx[b,t], o]
// idx[b,t] = sum_c ((x[b, aa[t,c]] - x[b, ab[t,c]]) > 0) << c
//
// R11: single-wavefront table loads. 512 threads/CTA, each thread owns 2
// output floats -> per-(t) load is LDG.32 (warp covers exactly 128B = 1
// wavefront, cross-LDG rate 1.0 cyc/wf) instead of LDG.64 (2 within-LDG
// wavefronts replaying at 2.07 cyc/wf). Table L1 cost/CTA ~530 -> ~256 cyc.
// Keeps: fp16 scratch, ballot-packed indices, depth-2 HADD2 tree.

#define B_SZ    16384
#define IN_F    1024
#define OUT_F   1024
#define T_CNT   16
#define C_CNT   8
#define R_CNT   256

#define TABLE_ELEMS (T_CNT * R_CNT * OUT_F)   // 4M elements

// 8 MB fp16 scratch copy of the table (device global: allocation-free).
__device__ __half g_table_h[TABLE_ELEMS];

// ---------------------------------------------------------------------------
// Pre-pass: fp32 table -> fp16 scratch. Each thread: 8 elems (32B in, 16B out).
// ---------------------------------------------------------------------------
__global__ __launch_bounds__(256)
void convert_table_kernel(const float4* __restrict__ table4)
{
    const int i = blockIdx.x * blockDim.x + threadIdx.x;   // 0 .. 512K-1
    const float4 v0 = __ldg(&table4[2 * i + 0]);
    const float4 v1 = __ldg(&table4[2 * i + 1]);
    half2 h[4];
    h[0] = __floats2half2_rn(v0.x, v0.y);
    h[1] = __floats2half2_rn(v0.z, v0.w);
    h[2] = __floats2half2_rn(v1.x, v1.y);
    h[3] = __floats2half2_rn(v1.z, v1.w);
    reinterpret_cast<uint4*>(g_table_h)[i] = *reinterpret_cast<const uint4*>(h);
}

// ---------------------------------------------------------------------------
// Reduce 8 half2 table values (one per t) with a depth-2 fp16 tree into a
// float2 accumulator. Same rounding structure as R10 (rel_err ~3.8e-4).
// ---------------------------------------------------------------------------
__device__ __forceinline__ void reduce8(const unsigned* __restrict__ v, float2& acc)
{
#define H2(u) (*reinterpret_cast<const half2*>(&(u)))
    half2 p0 = __hadd2(H2(v[0]), H2(v[1]));
    half2 p1 = __hadd2(H2(v[2]), H2(v[3]));
    half2 p2 = __hadd2(H2(v[4]), H2(v[5]));
    half2 p3 = __hadd2(H2(v[6]), H2(v[7]));
    half2 q0 = __hadd2(p0, p1);
    half2 q1 = __hadd2(p2, p3);
#undef H2
    const float2 f0 = __half22float2(q0);
    const float2 f1 = __half22float2(q1);
    acc.x += f0.x + f1.x;
    acc.y += f0.y + f1.y;
}

// ---------------------------------------------------------------------------
// Main: one CTA per batch, 512 threads, occ 4 (<=32 regs; 64 warps/SM).
//   Phase 0: stage x row (512 x float2 = 4KB, coalesced).
//   Phase 1: threads 0..127 one comparison each; ballot word = 4 packed
//            index bytes; one STS.32/warp.
//   Phase 2: thread tid owns output halves [2*tid, 2*tid+2). Two
//            front-batched waves of 8 LDG.32 + HADD2 tree. STG.64 out.
// ---------------------------------------------------------------------------
__global__ __launch_bounds__(512, 4)
void lut_gather_sum_kernel(const float2* __restrict__ x2,
                           const int* __restrict__ aa,
                           const int* __restrict__ ab,
                           float2* __restrict__ out2)
{
    __shared__ float s_x[IN_F];
    __shared__ __align__(16) unsigned s_pk[4];

    const int tid = threadIdx.x;
    const int b   = blockIdx.x;

    // Phase 0: stage x row (512 x float2 = 4KB, fully coalesced).
    reinterpret_cast<float2*>(s_x)[tid] = __ldg(&x2[(size_t)b * (IN_F / 2) + tid]);
    __syncthreads();

    // Phase 1: threads 0..127 each do one comparison (t = tid>>3, c = tid&7).
    // Warp w's ballot word is exactly the 4 packed index bytes for t=4w..4w+3.
    if (tid < 128) {
        const int lane = tid & 31;
        const int ia = __ldg(&aa[tid]);
        const int ib = __ldg(&ab[tid]);
        const float d = s_x[ia] - s_x[ib];
        const unsigned m = __ballot_sync(0xFFFFFFFFu, d > 0.0f);
        if (lane == 0) s_pk[tid >> 5] = m;
    }
    __syncthreads();

    // Phase 2: gather-sum from fp16 table (L2-resident), LDG.32 stream.
    const uint4 pk = *reinterpret_cast<const uint4*>(s_pk);  // 16 index bytes
    const char* base = reinterpret_cast<const char*>(g_table_h) + tid * 4;

    float2 acc = make_float2(0.f, 0.f);

    {   // wave A: t = 0..7 (index bytes in pk.x, pk.y)
        unsigned v[8];
#pragma unroll
        for (int t = 0; t < 8; t++) {
            const unsigned wd = (t < 4) ? pk.x : pk.y;
            const unsigned r = __byte_perm(wd, 0u, 0x4440 + (t & 3));
            // byte offset: t * (256 rows * 2048 B) + r * 2048 (+ tid*4 in base)
            v[t] = __ldg(reinterpret_cast<const unsigned*>(
                             base + (size_t)t * 524288u + r * 2048u));
        }
        reduce8(v, acc);
    }
    {   // wave B: t = 8..15 (index bytes in pk.z, pk.w)
        unsigned v[8];
#pragma unroll
        for (int t = 0; t < 8; t++) {
            const unsigned wd = (t < 4) ? pk.z : pk.w;
            const unsigned r = __byte_perm(wd, 0u, 0x4440 + (t & 3));
            v[t] = __ldg(reinterpret_cast<const unsigned*>(
                             base + (size_t)(t + 8) * 524288u + r * 2048u));
        }
        reduce8(v, acc);
    }

    out2[(size_t)b * (OUT_F / 2) + tid] = acc;
}

extern "C" void kernel_launch(void* const* d_in, const int* in_sizes, int n_in,
                              void* d_out, int out_size)
{
    const float2* x2     = (const float2*)d_in[0];  // (B, IN_F) fp32
    const float4* table4 = (const float4*)d_in[1];  // (T, R, OUT_F) fp32
    const int*    aa     = (const int*)   d_in[2];  // (T, C) int32
    const int*    ab     = (const int*)   d_in[3];  // (T, C) int32
    float2*       out2   = (float2*)      d_out;    // (B, OUT_F) fp32

    (void)in_sizes; (void)n_in; (void)out_size;

    // Pre-pass: table -> fp16 scratch (8 elems per thread)
    convert_table_kernel<<<TABLE_ELEMS / 8 / 256, 256>>>(table4);

    // Main gather-sum, 1 batch per CTA, 512 threads
    lut_gather_sum_kernel<<<B_SZ, 512>>>(x2, aa, ab, out2);
}

// round 12
// speedup vs baseline: 1.3968x; 1.3968x over previous
#include <cuda_runtime.h>
#include <cuda_fp16.h>
#include <cuda_pipeline.h>
#include <cstdint>

// LUTBlock: out[b,o] = sum_{t=0..15} table[t, idx[b,t], o]
// idx[b,t] = sum_c ((x[b, aa[t,c]] - x[b, ab[t,c]]) > 0) << c
//
// R12: persistent CTAs (grid = 148*8 = one wave, grid-stride over batches)
// to eliminate ~13 wave transitions; cp.async triple-buffered x prefetch
// (next-next batch, full-iter latency cover, no registers); one bar/iter.
// Gather phase identical to R10 (two 8x LDG.64 waves + HADD2 tree).

#define B_SZ    16384
#define IN_F    1024
#define OUT_F   1024
#define T_CNT   16
#define GRID_MAIN 1184          // 148 SMs x 8 CTAs: exactly one wave

#define TABLE_ELEMS (16 * 256 * 1024)   // 4M elements

// 8 MB fp16 scratch copy of the table (device global: allocation-free).
__device__ __half g_table_h[TABLE_ELEMS];

// ---------------------------------------------------------------------------
// Pre-pass: fp32 table -> fp16 scratch. Each thread: 8 elems (32B in, 16B out).
// ---------------------------------------------------------------------------
__global__ __launch_bounds__(256)
void convert_table_kernel(const float4* __restrict__ table4)
{
    const int i = blockIdx.x * blockDim.x + threadIdx.x;   // 0 .. 512K-1
    const float4 v0 = __ldg(&table4[2 * i + 0]);
    const float4 v1 = __ldg(&table4[2 * i + 1]);
    half2 h[4];
    h[0] = __floats2half2_rn(v0.x, v0.y);
    h[1] = __floats2half2_rn(v0.z, v0.w);
    h[2] = __floats2half2_rn(v1.x, v1.y);
    h[3] = __floats2half2_rn(v1.z, v1.w);
    reinterpret_cast<uint4*>(g_table_h)[i] = *reinterpret_cast<const uint4*>(h);
}

// ---------------------------------------------------------------------------
// Reduce 8 table values (uint2 of 4 halves) with a depth-2 fp16 tree,
// accumulating the two quad partials into fp32 acc. (R10, rel_err ~3.8e-4)
// ---------------------------------------------------------------------------
__device__ __forceinline__ void reduce8(const uint2* __restrict__ v, float4& acc)
{
#define H2(u) (*reinterpret_cast<const half2*>(&(u)))
    half2 p0 = __hadd2(H2(v[0].x), H2(v[1].x));
    half2 p1 = __hadd2(H2(v[2].x), H2(v[3].x));
    half2 p2 = __hadd2(H2(v[4].x), H2(v[5].x));
    half2 p3 = __hadd2(H2(v[6].x), H2(v[7].x));
    half2 qx0 = __hadd2(p0, p1);
    half2 qx1 = __hadd2(p2, p3);
    half2 r0 = __hadd2(H2(v[0].y), H2(v[1].y));
    half2 r1 = __hadd2(H2(v[2].y), H2(v[3].y));
    half2 r2 = __hadd2(H2(v[4].y), H2(v[5].y));
    half2 r3 = __hadd2(H2(v[6].y), H2(v[7].y));
    half2 qy0 = __hadd2(r0, r1);
    half2 qy1 = __hadd2(r2, r3);
#undef H2
    const float2 fx0 = __half22float2(qx0);
    const float2 fx1 = __half22float2(qx1);
    const float2 fy0 = __half22float2(qy0);
    const float2 fy1 = __half22float2(qy1);
    acc.x += fx0.x + fx1.x;
    acc.y += fx0.y + fx1.y;
    acc.z += fy0.x + fy1.x;
    acc.w += fy0.y + fy1.y;
}

// ---------------------------------------------------------------------------
// Persistent main kernel: 256 threads, occ 8. Grid-stride over batches with a
// depth-2 cp.async x-prefetch pipeline and one __syncthreads per batch.
//
// Per-iter schedule (buffers: s_x triple, s_pk double):
//   1. cp.async x[b+2*GRID] -> s_x[(p+2)%3]; commit
//   2. warps 0-3: ballot on s_x[p%3] -> s_pk[p&1]   (one STS.32/warp)
//   3. wait_prior(1)  (x[b+GRID]'s group complete), __syncthreads
//   4. gather from fp16 table using s_pk[p&1], STG out[b]
// Hazards are covered by the single bar (see analysis in commit message).
// ---------------------------------------------------------------------------
__global__ __launch_bounds__(256, 8)
void lut_persistent_kernel(const float4* __restrict__ x4,
                           const int* __restrict__ aa,
                           const int* __restrict__ ab,
                           float4* __restrict__ out4)
{
    __shared__ float s_x[3][IN_F];
    __shared__ __align__(16) unsigned s_pk[2][4];

    const int tid  = threadIdx.x;
    const int lane = tid & 31;

    // Loop-invariant anchors for the ballot warps.
    int ia = 0, ibx = 0;
    if (tid < 128) {
        ia  = __ldg(&aa[tid]);
        ibx = __ldg(&ab[tid]);
    }

    const char* tbase = reinterpret_cast<const char*>(g_table_h) + tid * 8;

    // Prologue: prefetch batches b0 and b0+GRID.
    const int b0 = blockIdx.x;
    __pipeline_memcpy_async(&reinterpret_cast<float4*>(s_x[0])[tid],
                            &x4[(size_t)b0 * (IN_F / 4) + tid], 16);
    __pipeline_commit();
    {
        const int b1 = b0 + GRID_MAIN;
        if (b1 < B_SZ)
            __pipeline_memcpy_async(&reinterpret_cast<float4*>(s_x[1])[tid],
                                    &x4[(size_t)b1 * (IN_F / 4) + tid], 16);
        __pipeline_commit();
    }
    __pipeline_wait_prior(1);   // b0's tile resident
    __syncthreads();

    int cur = 0;                // s_x buffer of current batch
    int par = 0;                // s_pk parity
    for (int b = b0; b < B_SZ; b += GRID_MAIN) {
        // 1. prefetch batch b + 2*GRID (depth-2 pipeline; empty group if OOB)
        {
            const int b2 = b + 2 * GRID_MAIN;
            int nxt2 = cur + 2; if (nxt2 >= 3) nxt2 -= 3;
            if (b2 < B_SZ)
                __pipeline_memcpy_async(&reinterpret_cast<float4*>(s_x[nxt2])[tid],
                                        &x4[(size_t)b2 * (IN_F / 4) + tid], 16);
            __pipeline_commit();
        }

        // 2. ballot: warp w's word = packed index bytes for t = 4w..4w+3
        if (tid < 128) {
            const float* xr = s_x[cur];
            const float d = xr[ia] - xr[ibx];
            const unsigned m = __ballot_sync(0xFFFFFFFFu, d > 0.0f);
            if (lane == 0) s_pk[par][tid >> 5] = m;
        }

        // 3. ensure next batch's x tile has landed; publish indices
        __pipeline_wait_prior(1);
        __syncthreads();

        // 4. gather-sum from fp16 table (L2-resident), two 8-load waves
        const uint4 pk = *reinterpret_cast<const uint4*>(s_pk[par]);
        float4 acc = make_float4(0.f, 0.f, 0.f, 0.f);
        {   // wave A: t = 0..7
            uint2 v[8];
#pragma unroll
            for (int t = 0; t < 8; t++) {
                const unsigned wd = (t < 4) ? pk.x : pk.y;
                const unsigned r = __byte_perm(wd, 0u, 0x4440 + (t & 3));
                v[t] = __ldg(reinterpret_cast<const uint2*>(
                                 tbase + (size_t)t * 524288u + r * 2048u));
            }
            reduce8(v, acc);
        }
        {   // wave B: t = 8..15
            uint2 v[8];
#pragma unroll
            for (int t = 0; t < 8; t++) {
                const unsigned wd = (t < 4) ? pk.z : pk.w;
                const unsigned r = __byte_perm(wd, 0u, 0x4440 + (t & 3));
                v[t] = __ldg(reinterpret_cast<const uint2*>(
                                 tbase + (size_t)(t + 8) * 524288u + r * 2048u));
            }
            reduce8(v, acc);
        }
        out4[(size_t)b * (OUT_F / 4) + tid] = acc;

        // advance pipeline state
        cur = (cur + 1 == 3) ? 0 : cur + 1;
        par ^= 1;
    }
}

extern "C" void kernel_launch(void* const* d_in, const int* in_sizes, int n_in,
                              void* d_out, int out_size)
{
    const float4* x4     = (const float4*)d_in[0];  // (B, IN_F) fp32
    const float4* table4 = (const float4*)d_in[1];  // (T, R, OUT_F) fp32
    const int*    aa     = (const int*)   d_in[2];  // (T, C) int32
    const int*    ab     = (const int*)   d_in[3];  // (T, C) int32
    float4*       out4   = (float4*)      d_out;    // (B, OUT_F) fp32

    (void)in_sizes; (void)n_in; (void)out_size;

    // Pre-pass: table -> fp16 scratch (8 elems per thread)
    convert_table_kernel<<<TABLE_ELEMS / 8 / 256, 256>>>(table4);

    // Persistent main: one wave of CTAs, grid-stride over batches
    lut_persistent_kernel<<<GRID_MAIN, 256>>>(x4, aa, ab, out4);
}